// round 2
// baseline (speedup 1.0000x reference)
#include <cuda_runtime.h>

#define BS   128
#define NR   3
#define CD   64
#define CG   3
#define CH   256
#define KIN  67
#define KP   68          // padded k
#define HW   1024
#define PB   64          // pixels per tile
#define TPB  2           // tiles per block
#define THREADS 512
#define NBLOCKS (BS * (HW / PB) / TPB)   // 1024

typedef unsigned long long u64;

__device__ __forceinline__ void fma2(u64 &d, u64 a, u64 b) {
    asm("fma.rn.f32x2 %0, %1, %2, %0;" : "+l"(d) : "l"(a), "l"(b));
}
__device__ __forceinline__ u64 pack2(float lo, float hi) {
    u64 d; asm("mov.b64 %0, {%1, %2};" : "=l"(d) : "f"(lo), "f"(hi)); return d;
}
__device__ __forceinline__ void unpack2(u64 v, float &lo, float &hi) {
    asm("mov.b64 {%0, %1}, %2;" : "=f"(lo), "=f"(hi) : "l"(v));
}

#define XROW  68                       // floats per xs row (34 u64, even -> 16B aligned)
#define WST_N (KP * 4 * 32)            // 8704 ulonglong2
#define XS_N  (NR * KP * XROW)         // 13872 floats
#define SMEM_BYTES (WST_N * 16 + XS_N * 4 + 2 * CH * 4)  // 196800

extern __shared__ unsigned char smem_raw[];

__global__ __launch_bounds__(THREADS, 1)
void qnn_kernel(const float* __restrict__ data, const float* __restrict__ gt,
                const float* __restrict__ W1, const float* __restrict__ b1,
                const float* __restrict__ W3, const float* __restrict__ b3,
                float* __restrict__ out)
{
    ulonglong2* wst = (ulonglong2*)smem_raw;             // [k][j][lane] dup'd weight pairs
    float* xs  = (float*)(smem_raw + WST_N * 16);        // [n][k][XROW]
    float* b1s = xs + XS_N;
    float* w3s = b1s + CH;

    const int tid  = threadIdx.x;
    const int lane = tid & 31;
    const int wp   = tid >> 5;          // warp id = pixel group (4 px each)
    const int b     = blockIdx.x >> 3;
    const int tile0 = blockIdx.x & 7;

    // ---- one-time: duplicated, transposed W1 into smem ----
    for (int i = tid; i < WST_N; i += THREADS) {
        int k = i >> 7;
        int j = (i >> 5) & 3;
        int l = i & 31;
        int o0 = l * 8 + j * 2;
        float w0 = 0.f, w1 = 0.f;
        if (k < KIN) { w0 = W1[o0 * KIN + k]; w1 = W1[(o0 + 1) * KIN + k]; }
        ulonglong2 v; v.x = pack2(w0, w0); v.y = pack2(w1, w1);
        wst[i] = v;
    }
    for (int i = tid; i < CH; i += THREADS) { b1s[i] = b1[i]; w3s[i] = W3[i]; }
    const float bias3 = b3[0];

    float* out_w = out + (size_t)BS * CD * HW;

    for (int t = 0; t < TPB; t++) {
        const int p0 = (tile0 + t * 8) * PB;

        // ---- stage x tile: [n][k][px], rows padded to XROW=68 floats ----
        __syncthreads();   // (t==0: covers weight stores too; t>0: xs safe to overwrite)
        for (int i = tid; i < XS_N; i += THREADS) {
            int n  = i / (KP * XROW);
            int r  = i - n * (KP * XROW);
            int k  = r / XROW;
            int px = r - k * XROW;
            float v = 0.f;
            if (px < PB) {
                if (k < CD)       v = data[((size_t)(b * NR + n) * CD + k) * HW + p0 + px];
                else if (k < KIN) v = gt[((size_t)b * CG + (k - CD)) * HW + p0 + px];
            }
            xs[i] = v;
        }
        __syncthreads();

        float sg[NR][4];
        #pragma unroll
        for (int n = 0; n < NR; n++) {
            u64 acc[4][2][2];
            #pragma unroll
            for (int j = 0; j < 4; j++) { acc[j][0][0]=0; acc[j][0][1]=0; acc[j][1][0]=0; acc[j][1][1]=0; }

            const u64* xk = (const u64*)xs + (size_t)n * KP * (XROW / 2) + wp * 2;
            const ulonglong2* wk = wst + lane;

            #pragma unroll 4
            for (int k = 0; k < KP; k++) {
                ulonglong2 xv = *(const ulonglong2*)(xk + (size_t)k * (XROW / 2));
                #pragma unroll
                for (int j = 0; j < 4; j++) {
                    ulonglong2 wv = wk[(k * 4 + j) * 32];
                    fma2(acc[j][0][0], wv.x, xv.x);
                    fma2(acc[j][0][1], wv.x, xv.y);
                    fma2(acc[j][1][0], wv.y, xv.x);
                    fma2(acc[j][1][1], wv.y, xv.y);
                }
            }

            // per-thread partial: sum over this lane's 8 outputs of relu(.)*w3
            float s0 = 0.f, s1 = 0.f, s2 = 0.f, s3 = 0.f;
            #pragma unroll
            for (int j = 0; j < 4; j++) {
                #pragma unroll
                for (int tt = 0; tt < 2; tt++) {
                    int o = lane * 8 + j * 2 + tt;
                    float bb = b1s[o], w3v = w3s[o];
                    float a0, a1, a2, a3;
                    unpack2(acc[j][tt][0], a0, a1);
                    unpack2(acc[j][tt][1], a2, a3);
                    s0 = fmaf(fmaxf(a0 + bb, 0.f), w3v, s0);
                    s1 = fmaf(fmaxf(a1 + bb, 0.f), w3v, s1);
                    s2 = fmaf(fmaxf(a2 + bb, 0.f), w3v, s2);
                    s3 = fmaf(fmaxf(a3 + bb, 0.f), w3v, s3);
                }
            }
            // reduce across the 32 lanes (32 output-groups)
            #pragma unroll
            for (int off = 16; off; off >>= 1) {
                s0 += __shfl_xor_sync(0xffffffffu, s0, off);
                s1 += __shfl_xor_sync(0xffffffffu, s1, off);
                s2 += __shfl_xor_sync(0xffffffffu, s2, off);
                s3 += __shfl_xor_sync(0xffffffffu, s3, off);
            }
            sg[n][0] = 1.f / (1.f + __expf(-(s0 + bias3)));
            sg[n][1] = 1.f / (1.f + __expf(-(s1 + bias3)));
            sg[n][2] = 1.f / (1.f + __expf(-(s2 + bias3)));
            sg[n][3] = 1.f / (1.f + __expf(-(s3 + bias3)));
        }

        // normalize over refs
        float wn[NR][4];
        #pragma unroll
        for (int i = 0; i < 4; i++) {
            float inv = 1.f / (sg[0][i] + sg[1][i] + sg[2][i]);
            wn[0][i] = sg[0][i] * inv;
            wn[1][i] = sg[1][i] * inv;
            wn[2][i] = sg[2][i] * inv;
        }

        const int pbase = p0 + wp * 4;

        // write w: lanes 0..5 write one u64 pair each
        if (lane < 6) {
            int n = lane >> 1, pr = lane & 1;
            *(u64*)(out_w + ((size_t)b * NR + n) * HW + pbase + pr * 2)
                = pack2(wn[n][pr * 2], wn[n][pr * 2 + 1]);
        }

        // z epilogue: reuse x tile in smem. lane -> (c = it*8 + lane/4, px = lane&3)
        const int px = lane & 3;
        float wsel0 = px == 0 ? wn[0][0] : px == 1 ? wn[0][1] : px == 2 ? wn[0][2] : wn[0][3];
        float wsel1 = px == 0 ? wn[1][0] : px == 1 ? wn[1][1] : px == 2 ? wn[1][2] : wn[1][3];
        float wsel2 = px == 0 ? wn[2][0] : px == 1 ? wn[2][1] : px == 2 ? wn[2][2] : wn[2][3];
        const int coff = lane >> 2;
        #pragma unroll
        for (int it = 0; it < 8; it++) {
            int c = it * 8 + coff;
            float z = 0.f;
            z = fmaf(xs[(0 * KP + c) * XROW + wp * 4 + px], wsel0, z);
            z = fmaf(xs[(1 * KP + c) * XROW + wp * 4 + px], wsel1, z);
            z = fmaf(xs[(2 * KP + c) * XROW + wp * 4 + px], wsel2, z);
            out[((size_t)b * CD + c) * HW + pbase + px] = z;
        }
    }
}

extern "C" void kernel_launch(void* const* d_in, const int* in_sizes, int n_in,
                              void* d_out, int out_size) {
    const float* data = (const float*)d_in[0];
    const float* gt   = (const float*)d_in[1];
    const float* W1   = (const float*)d_in[2];
    const float* b1   = (const float*)d_in[3];
    const float* W3   = (const float*)d_in[4];
    const float* b3   = (const float*)d_in[5];
    float* out = (float*)d_out;

    cudaFuncSetAttribute(qnn_kernel, cudaFuncAttributeMaxDynamicSharedMemorySize,
                         SMEM_BYTES);
    qnn_kernel<<<NBLOCKS, THREADS, SMEM_BYTES>>>(data, gt, W1, b1, W3, b3, out);
}

// round 3
// speedup vs baseline: 1.0750x; 1.0750x over previous
#include <cuda_runtime.h>

#define BS 128
#define NR 3
#define CD 64
#define CG 3
#define CH 256
#define KIN 67
#define KP 68            // KIN + 1 bias row
#define HW 1024
#define PXT 64           // pixels per tile
#define TPB 2
#define THREADS 256
#define NBLK (BS * HW / (PXT * TPB))   // 1024

typedef unsigned long long u64;

__device__ __forceinline__ void fma2(u64 &d, u64 a, u64 b) {
    asm("fma.rn.f32x2 %0, %1, %2, %0;" : "+l"(d) : "l"(a), "l"(b));
}
__device__ __forceinline__ u64 add2(u64 a, u64 b) {
    u64 d; asm("add.rn.f32x2 %0, %1, %2;" : "=l"(d) : "l"(a), "l"(b)); return d;
}
__device__ __forceinline__ u64 pack2(float lo, float hi) {
    u64 d; asm("mov.b64 %0, {%1, %2};" : "=l"(d) : "f"(lo), "f"(hi)); return d;
}
__device__ __forceinline__ void unpack2(u64 v, float &lo, float &hi) {
    asm("mov.b64 {%0, %1}, %2;" : "=f"(lo), "=f"(hi) : "l"(v));
}

// ---- shared memory layout (bytes) ----
// ws   : u64 [KP][CH]  dup'd weights            139264
// ovl  : raw W1 [256][69] (70656) overlaid with xs [3][KP][68] (55488)
// b1s  : 1024   w3s : 1024
// sred : [3][8][64] f32 = 6144
// sgm  : [3][64] = 768   wnm : [3][64] = 768
#define OFF_WS   0
#define OFF_OVL  139264
#define OFF_B1   (OFF_OVL + 70656)
#define OFF_W3   (OFF_B1 + 1024)
#define OFF_SRED (OFF_W3 + 1024)
#define OFF_SGM  (OFF_SRED + 6144)
#define OFF_WNM  (OFF_SGM + 768)
#define SMEM_BYTES (OFF_WNM + 768)    // 219648

extern __shared__ unsigned char smem_raw[];

__global__ __launch_bounds__(THREADS, 1)
void qnn_kernel(const float* __restrict__ data, const float* __restrict__ gt,
                const float* __restrict__ W1, const float* __restrict__ b1,
                const float* __restrict__ W3, const float* __restrict__ b3,
                float* __restrict__ out)
{
    u64*   ws   = (u64*)(smem_raw + OFF_WS);
    float* raw  = (float*)(smem_raw + OFF_OVL);   // W1 bounce, padded rows of 69
    float* xs   = (float*)(smem_raw + OFF_OVL);   // x tile (reuses raw region)
    float* b1s  = (float*)(smem_raw + OFF_B1);
    float* w3s  = (float*)(smem_raw + OFF_W3);
    float* sred = (float*)(smem_raw + OFF_SRED);
    float* sgm  = (float*)(smem_raw + OFF_SGM);
    float* wnm  = (float*)(smem_raw + OFF_WNM);

    const int tid  = threadIdx.x;
    const int lane = tid & 31;
    const int warp = tid >> 5;        // 0..7 -> outputs [warp*32, warp*32+32)
    const int og   = lane & 3;        // output group within warp
    const int pg   = lane >> 2;       // pixel group (8 px each)
    const int b     = blockIdx.x >> 3;
    const int tile0 = blockIdx.x & 7;

    // ---- stage b1/w3 + W1 bounce (coalesced gmem) ----
    for (int i = tid; i < CH; i += THREADS) { b1s[i] = b1[i]; w3s[i] = W3[i]; }
    for (int it = 0; it < KIN; it++) {            // 67*256 = 17152 elements
        int i = it * THREADS + tid;
        int o = i / KIN, k = i - o * KIN;
        raw[o * 69 + k] = W1[i];
    }
    __syncthreads();
    // transpose + duplicate: ws[k][o] = {w,w}; k==67 row carries b1
    for (int it = 0; it < KP; it++) {
        int i = it * THREADS + tid;
        int k = i >> 8, o = i & 255;
        float w = (k < KIN) ? raw[o * 69 + k] : b1s[o];
        ws[k * CH + o] = pack2(w, w);
    }
    const float bias3 = b3[0];
    float* out_w = out + (size_t)BS * CD * HW;

    for (int t = 0; t < TPB; t++) {
        const int p0 = (tile0 + t * 8) * PXT;

        __syncthreads();   // t==0: transpose done before xs overwrites raw; t>0: xs free
        // ---- stage x tile: xs[n*KP+k][px], k==67 row = 1.0 (bias) ----
        for (int it = 0; it < 51; it++) {          // 3*68*64/256 = 51 exact
            int i  = it * THREADS + tid;
            int px = i & 63;
            int r  = i >> 6;                        // n*KP + k
            int n  = r / KP;
            int k  = r - n * KP;
            float v;
            if (k < CD)       v = data[(((size_t)(b * NR + n)) * CD + k) * HW + p0 + px];
            else if (k < KIN) v = gt[((size_t)b * CG + (k - CD)) * HW + p0 + px];
            else              v = 1.0f;
            xs[r * 68 + px] = v;
        }
        __syncthreads();

        #pragma unroll
        for (int n = 0; n < NR; n++) {
            u64 acc[4][2][4];
            #pragma unroll
            for (int j = 0; j < 4; j++)
                #pragma unroll
                for (int e = 0; e < 2; e++)
                    #pragma unroll
                    for (int u = 0; u < 4; u++) acc[j][e][u] = 0ull;

            const ulonglong2* xb = (const ulonglong2*)xs + (size_t)n * KP * 17 + pg * 2;
            const ulonglong2* wb = (const ulonglong2*)ws + warp * 16 + og;

            #pragma unroll 4
            for (int k = 0; k < KP; k++) {
                ulonglong2 xv0 = xb[k * 17];
                ulonglong2 xv1 = xb[k * 17 + 1];
                #pragma unroll
                for (int j = 0; j < 4; j++) {
                    ulonglong2 wv = wb[k * 128 + j * 4];
                    fma2(acc[j][0][0], wv.x, xv0.x);
                    fma2(acc[j][0][1], wv.x, xv0.y);
                    fma2(acc[j][0][2], wv.x, xv1.x);
                    fma2(acc[j][0][3], wv.x, xv1.y);
                    fma2(acc[j][1][0], wv.y, xv0.x);
                    fma2(acc[j][1][1], wv.y, xv0.y);
                    fma2(acc[j][1][2], wv.y, xv1.x);
                    fma2(acc[j][1][3], wv.y, xv1.y);
                }
            }

            // relu + w3 partial sums over this thread's 8 outputs (bias already in acc)
            u64 spx[4] = {0ull, 0ull, 0ull, 0ull};
            #pragma unroll
            for (int j = 0; j < 4; j++) {
                #pragma unroll
                for (int e = 0; e < 2; e++) {
                    int o = warp * 32 + j * 8 + og * 2 + e;
                    float w3v = w3s[o];
                    u64 w32 = pack2(w3v, w3v);
                    #pragma unroll
                    for (int u = 0; u < 4; u++) {
                        float a0, a1;
                        unpack2(acc[j][e][u], a0, a1);
                        a0 = fmaxf(a0, 0.f);
                        a1 = fmaxf(a1, 0.f);
                        fma2(spx[u], pack2(a0, a1), w32);
                    }
                }
            }
            // reduce across the 4 output-groups (lane bits 0..1)
            #pragma unroll
            for (int u = 0; u < 4; u++) {
                spx[u] = add2(spx[u], __shfl_xor_sync(0xffffffffu, spx[u], 1));
                spx[u] = add2(spx[u], __shfl_xor_sync(0xffffffffu, spx[u], 2));
            }
            // lane og stores u64 #og of its pixel group
            ((u64*)sred)[(n * 8 + warp) * 32 + lane] = spx[og];
        }
        __syncthreads();

        // cross-warp reduce (8 partials) + sigmoid
        if (tid < 192) {
            int n = tid >> 6, px = tid & 63;
            const float* sp = sred + n * 8 * 64 + px;
            float s = bias3;
            #pragma unroll
            for (int w = 0; w < 8; w++) s += sp[w * 64];
            sgm[n * 64 + px] = 1.f / (1.f + __expf(-s));
        }
        __syncthreads();

        // normalize over refs + write w
        if (tid < 64) {
            int px = tid;
            float s0 = sgm[px], s1 = sgm[64 + px], s2 = sgm[128 + px];
            float inv = 1.f / (s0 + s1 + s2);
            float w0 = s0 * inv, w1 = s1 * inv, w2 = s2 * inv;
            wnm[px] = w0; wnm[64 + px] = w1; wnm[128 + px] = w2;
            out_w[((size_t)b * NR + 0) * HW + p0 + px] = w0;
            out_w[((size_t)b * NR + 1) * HW + p0 + px] = w1;
            out_w[((size_t)b * NR + 2) * HW + p0 + px] = w2;
        }
        __syncthreads();

        // z epilogue: reuse x tile in smem
        {
            int px = tid & 63, c0 = tid >> 6;
            float w0 = wnm[px], w1 = wnm[64 + px], w2 = wnm[128 + px];
            #pragma unroll
            for (int it = 0; it < 16; it++) {
                int c = c0 * 16 + it;
                float z = xs[(0 * KP + c) * 68 + px] * w0;
                z = fmaf(xs[(1 * KP + c) * 68 + px], w1, z);
                z = fmaf(xs[(2 * KP + c) * 68 + px], w2, z);
                out[((size_t)b * CD + c) * HW + p0 + px] = z;
            }
        }
    }
}

extern "C" void kernel_launch(void* const* d_in, const int* in_sizes, int n_in,
                              void* d_out, int out_size) {
    const float* data = (const float*)d_in[0];
    const float* gt   = (const float*)d_in[1];
    const float* W1   = (const float*)d_in[2];
    const float* b1   = (const float*)d_in[3];
    const float* W3   = (const float*)d_in[4];
    const float* b3   = (const float*)d_in[5];
    float* out = (float*)d_out;

    cudaFuncSetAttribute(qnn_kernel, cudaFuncAttributeMaxDynamicSharedMemorySize,
                         SMEM_BYTES);
    qnn_kernel<<<NBLK, THREADS, SMEM_BYTES>>>(data, gt, W1, b1, W3, b3, out);
}

// round 5
// speedup vs baseline: 1.1592x; 1.0783x over previous
#include <cuda_runtime.h>

#define BS 128
#define NR 3
#define CD 64
#define CG 3
#define CH 256
#define KIN 67
#define KP 68            // KIN + bias row
#define HW 1024
#define PXT 64
#define TPB 4
#define THREADS 512
#define NBLK (BS * (HW / PXT) / TPB)   // 512

typedef unsigned long long u64;

__device__ __forceinline__ void fma2(u64 &d, u64 a, u64 b) {
    asm("fma.rn.f32x2 %0, %1, %2, %0;" : "+l"(d) : "l"(a), "l"(b));
}
__device__ __forceinline__ u64 pack2(float lo, float hi) {
    u64 d; asm("mov.b64 %0, {%1, %2};" : "=l"(d) : "f"(lo), "f"(hi)); return d;
}
__device__ __forceinline__ void unpack2(u64 v, float &lo, float &hi) {
    asm("mov.b64 {%0, %1}, %2;" : "=f"(lo), "=f"(hi) : "l"(v));
}

// ---- smem layout (bytes) ----
// ws  : float [KP][CH] transposed weights (k=67 row = b1)      69632
// xs  : u64  [NR*KP][64] duplicated x pairs {x,x}             104448
//       (overlaid during preamble with raw W1 [256][69] = 70656)
// b1s/w3s: 1024+1024, sred: 3*8*64*4=6144, sgm: 768, wnm: 768
#define OFF_WS   0
#define OFF_XS   69632
#define OFF_B1   (OFF_XS + 104448)
#define OFF_W3   (OFF_B1 + 1024)
#define OFF_SRED (OFF_W3 + 1024)
#define OFF_SGM  (OFF_SRED + 6144)
#define OFF_WNM  (OFF_SGM + 768)
#define SMEM_BYTES (OFF_WNM + 768)   // 183808

extern __shared__ unsigned char smem_raw[];

__global__ __launch_bounds__(THREADS, 1)
void qnn_kernel(const float* __restrict__ data, const float* __restrict__ gt,
                const float* __restrict__ W1, const float* __restrict__ b1,
                const float* __restrict__ W3, const float* __restrict__ b3,
                float* __restrict__ out)
{
    float* wsf  = (float*)(smem_raw + OFF_WS);    // [KP][256]
    u64*   xs   = (u64*)(smem_raw + OFF_XS);      // [NR*KP][64] dup pairs
    float* raw  = (float*)(smem_raw + OFF_XS);    // W1 bounce [256][69]
    float* b1s  = (float*)(smem_raw + OFF_B1);
    float* w3s  = (float*)(smem_raw + OFF_W3);
    float* sred = (float*)(smem_raw + OFF_SRED);  // [3][8][64]
    float* sgm  = (float*)(smem_raw + OFF_SGM);
    float* wnm  = (float*)(smem_raw + OFF_WNM);

    const int tid  = threadIdx.x;
    const int lane = tid & 31;
    const int warp = tid >> 5;       // 0..15
    const int wo   = warp & 7;       // output-block: outpairs [wo*16, wo*16+16)
    const int wp   = warp >> 3;      // pixel-block: px [wp*32, wp*32+32)
    const int og   = lane & 3;       // -> outpairs wo*16 + og*4 .. +4
    const int pg   = lane >> 2;      // -> px wp*32 + pg*4 .. +4
    const int b     = blockIdx.x >> 2;
    const int tile0 = blockIdx.x & 3;

    // ---- preamble: b1/w3, W1 bounce (coalesced), transpose into wsf ----
    if (tid < CH) { b1s[tid] = b1[tid]; w3s[tid] = W3[tid]; }
    #pragma unroll 1
    for (int it = 0; it < 34; it++) {
        int i = it * THREADS + tid;
        if (i < CH * KIN) {
            int o = i / KIN, k = i - o * KIN;
            raw[o * 69 + k] = W1[i];
        }
    }
    __syncthreads();
    #pragma unroll 1
    for (int it = 0; it < 34; it++) {
        int i = it * THREADS + tid;
        int k = i >> 8, o = i & 255;
        wsf[k * CH + o] = (k < KIN) ? raw[o * 69 + k] : b1s[o];
    }
    const float bias3 = b3[0];
    float* out_w = out + (size_t)BS * CD * HW;

    for (int t = 0; t < TPB; t++) {
        const int p0 = (tile0 + t * 4) * PXT;

        __syncthreads();   // t==0: transpose reads of raw done; t>0: xs readers done
        // ---- stage x tile duplicated: xs[n*KP+k][px] = {x,x}; k==67 row = {1,1} ----
        #pragma unroll 1
        for (int it = 0; it < 26; it++) {
            int i = it * THREADS + tid;
            if (i < NR * KP * 64) {
                int px = i & 63;
                int r  = i >> 6;
                int n  = r / KP;
                int k  = r - n * KP;
                float v;
                if (k < CD)       v = data[(((size_t)(b * NR + n)) * CD + k) * HW + p0 + px];
                else if (k < KIN) v = gt[((size_t)b * CG + (k - CD)) * HW + p0 + px];
                else              v = 1.0f;
                xs[i] = pack2(v, v);
            }
        }
        __syncthreads();

        #pragma unroll
        for (int n = 0; n < NR; n++) {
            // acc[j][u] = {out_{2op}(px_u), out_{2op+1}(px_u)}, op = wo*16+og*4+j
            u64 acc[4][4];
            #pragma unroll
            for (int j = 0; j < 4; j++)
                #pragma unroll
                for (int u = 0; u < 4; u++) acc[j][u] = 0ull;

            const ulonglong2* xb = (const ulonglong2*)(xs + (size_t)n * KP * 64 + wp * 32 + pg * 4);
            // FIX: pair index wo*16+og*4 -> ulonglong2 index (wo*16+og*4)/2 = wo*8+og*2
            const ulonglong2* wb = (const ulonglong2*)wsf + wo * 8 + og * 2;

            #pragma unroll 4
            for (int k = 0; k < KP; k++) {
                ulonglong2 x01 = xb[k * 32];
                ulonglong2 x23 = xb[k * 32 + 1];
                ulonglong2 w01 = wb[k * 64];      // pairs op+0, op+1
                ulonglong2 w23 = wb[k * 64 + 1];  // pairs op+2, op+3
                fma2(acc[0][0], w01.x, x01.x);
                fma2(acc[0][1], w01.x, x01.y);
                fma2(acc[0][2], w01.x, x23.x);
                fma2(acc[0][3], w01.x, x23.y);
                fma2(acc[1][0], w01.y, x01.x);
                fma2(acc[1][1], w01.y, x01.y);
                fma2(acc[1][2], w01.y, x23.x);
                fma2(acc[1][3], w01.y, x23.y);
                fma2(acc[2][0], w23.x, x01.x);
                fma2(acc[2][1], w23.x, x01.y);
                fma2(acc[2][2], w23.x, x23.x);
                fma2(acc[2][3], w23.x, x23.y);
                fma2(acc[3][0], w23.y, x01.x);
                fma2(acc[3][1], w23.y, x01.y);
                fma2(acc[3][2], w23.y, x23.x);
                fma2(acc[3][3], w23.y, x23.y);
            }

            // relu + w3 partial sums: s[px] over this thread's 8 outputs
            float s[4] = {0.f, 0.f, 0.f, 0.f};
            #pragma unroll
            for (int j = 0; j < 4; j++) {
                int o2 = (wo * 16 + og * 4 + j) * 2;
                float w3a = w3s[o2], w3b = w3s[o2 + 1];
                #pragma unroll
                for (int u = 0; u < 4; u++) {
                    float a0, a1;
                    unpack2(acc[j][u], a0, a1);
                    s[u] = fmaf(fmaxf(a0, 0.f), w3a, s[u]);
                    s[u] = fmaf(fmaxf(a1, 0.f), w3b, s[u]);
                }
            }
            // reduce over the 4 og lanes
            #pragma unroll
            for (int u = 0; u < 4; u++) {
                s[u] += __shfl_xor_sync(0xffffffffu, s[u], 1);
                s[u] += __shfl_xor_sync(0xffffffffu, s[u], 2);
            }
            // lane og stores px = wp*32 + pg*4 + og
            sred[(n * 8 + wo) * 64 + wp * 32 + pg * 4 + og] = s[og];
        }
        __syncthreads();

        // cross-warp reduce over 8 output-blocks + sigmoid
        if (tid < 192) {
            int n = tid >> 6, px = tid & 63;
            const float* sp = sred + n * 8 * 64 + px;
            float v = bias3;
            #pragma unroll
            for (int w = 0; w < 8; w++) v += sp[w * 64];
            sgm[n * 64 + px] = 1.f / (1.f + __expf(-v));
        }
        __syncthreads();

        if (tid < 64) {
            int px = tid;
            float s0 = sgm[px], s1 = sgm[64 + px], s2 = sgm[128 + px];
            float inv = 1.f / (s0 + s1 + s2);
            float w0 = s0 * inv, w1 = s1 * inv, w2 = s2 * inv;
            wnm[px] = w0; wnm[64 + px] = w1; wnm[128 + px] = w2;
            out_w[((size_t)b * NR + 0) * HW + p0 + px] = w0;
            out_w[((size_t)b * NR + 1) * HW + p0 + px] = w1;
            out_w[((size_t)b * NR + 2) * HW + p0 + px] = w2;
        }
        __syncthreads();

        // z epilogue: reuse x tile (dup pairs -> take lo lane)
        {
            int px = tid & 63;
            int cb = (tid >> 6) * 8;            // 8 channels per thread
            float w0 = wnm[px], w1 = wnm[64 + px], w2 = wnm[128 + px];
            #pragma unroll
            for (int it = 0; it < 8; it++) {
                int c = cb + it;
                float x0, x1, x2, dummy;
                unpack2(xs[(size_t)(0 * KP + c) * 64 + px], x0, dummy);
                unpack2(xs[(size_t)(1 * KP + c) * 64 + px], x1, dummy);
                unpack2(xs[(size_t)(2 * KP + c) * 64 + px], x2, dummy);
                float z = x0 * w0;
                z = fmaf(x1, w1, z);
                z = fmaf(x2, w2, z);
                out[((size_t)b * CD + c) * HW + p0 + px] = z;
            }
        }
    }
}

extern "C" void kernel_launch(void* const* d_in, const int* in_sizes, int n_in,
                              void* d_out, int out_size) {
    const float* data = (const float*)d_in[0];
    const float* gt   = (const float*)d_in[1];
    const float* W1   = (const float*)d_in[2];
    const float* b1   = (const float*)d_in[3];
    const float* W3   = (const float*)d_in[4];
    const float* b3   = (const float*)d_in[5];
    float* out = (float*)d_out;

    cudaFuncSetAttribute(qnn_kernel, cudaFuncAttributeMaxDynamicSharedMemorySize,
                         SMEM_BYTES);
    qnn_kernel<<<NBLK, THREADS, SMEM_BYTES>>>(data, gt, W1, b1, W3, b3, out);
}